// round 3
// baseline (speedup 1.0000x reference)
#include <cuda_runtime.h>
#include <cstdint>

#define B 8
#define N 32768
#define K 1024
#define C 128
#define CSIZE 16                 // CTAs per cluster (one cluster per batch)
#define T 512                    // threads per CTA
#define PPT 4                    // points per thread (N / (CSIZE*T))
#define NW 16                    // warps per CTA
#define FULL 0xffffffffu
#define TXB (CSIZE * 24)         // 16 CTAs x 3 st.async.b64 each

typedef unsigned long long u64;

// FPS-selected indices, [B][K]
__device__ int g_fps_idx[B * K];

struct alignas(8) Slot {
    unsigned d;    // +0  fp32 bits of min-dist (nonneg -> uint order-isomorphic)
    int i;         // +4  point index (0..N-1, 15 bits)
    float x, y;    // +8, +12
    float z;       // +16
    unsigned pad;  // +20
};

// ---------------- PTX helpers ----------------
__device__ __forceinline__ unsigned smem_u32(const void* p) {
    return (unsigned)__cvta_generic_to_shared(p);
}
__device__ __forceinline__ unsigned mapa_u32(unsigned addr, unsigned rank) {
    unsigned r;
    asm("mapa.shared::cluster.u32 %0, %1, %2;" : "=r"(r) : "r"(addr), "r"(rank));
    return r;
}
__device__ __forceinline__ u64 pk2f(float lo, float hi) {
    u64 v; asm("mov.b64 %0, {%1, %2};" : "=l"(v) : "f"(lo), "f"(hi)); return v;
}
__device__ __forceinline__ u64 pk2u(unsigned lo, unsigned hi) {
    u64 v; asm("mov.b64 %0, {%1, %2};" : "=l"(v) : "r"(lo), "r"(hi)); return v;
}
__device__ __forceinline__ void upk2f(float& lo, float& hi, u64 v) {
    asm("mov.b64 {%0, %1}, %2;" : "=f"(lo), "=f"(hi) : "l"(v));
}
__device__ __forceinline__ u64 addx2(u64 a, u64 b) {
    u64 r; asm("add.rn.f32x2 %0, %1, %2;" : "=l"(r) : "l"(a), "l"(b)); return r;
}
__device__ __forceinline__ u64 mulx2(u64 a, u64 b) {
    u64 r; asm("mul.rn.f32x2 %0, %1, %2;" : "=l"(r) : "l"(a), "l"(b)); return r;
}
__device__ __forceinline__ void mbar_init(unsigned bar, unsigned cnt) {
    asm volatile("mbarrier.init.shared.b64 [%0], %1;" :: "r"(bar), "r"(cnt) : "memory");
}
__device__ __forceinline__ void mbar_expect(unsigned bar, unsigned tx) {
    asm volatile("mbarrier.arrive.expect_tx.shared.b64 _, [%0], %1;"
                 :: "r"(bar), "r"(tx) : "memory");
}
__device__ __forceinline__ void st_async64(unsigned raddr, u64 v, unsigned rbar) {
    asm volatile(
        "st.async.shared::cluster.mbarrier::complete_tx::bytes.b64 [%0], %1, [%2];"
        :: "r"(raddr), "l"(v), "r"(rbar) : "memory");
}
__device__ __forceinline__ void mbar_wait(unsigned bar, unsigned ph) {
    asm volatile(
        "{\n\t"
        ".reg .pred P;\n\t"
        "WL_%=:\n\t"
        "mbarrier.try_wait.parity.acquire.cluster.shared::cta.b64 P, [%0], %1, 0x989680;\n\t"
        "@P bra WD_%=;\n\t"
        "bra WL_%=;\n\t"
        "WD_%=:\n\t"
        "}"
        :: "r"(bar), "r"(ph) : "memory");
}
__device__ __forceinline__ void cluster_sync_all() {
    asm volatile("barrier.cluster.arrive.aligned;" ::: "memory");
    asm volatile("barrier.cluster.wait.aligned;" ::: "memory");
}

__global__ void __launch_bounds__(T, 1)
fps_kernel(const float* __restrict__ xyz) {
    __shared__ Slot s_warp[NW];
    __shared__ Slot s_cl[2][CSIZE];   // double-buffered cross-CTA candidate slots
    __shared__ u64 s_bar[2];          // double-buffered mbarriers

    const int t = threadIdx.x;
    const int lane = t & 31;
    const int w = t >> 5;
    const int blk = blockIdx.x;
    const int b = blk / CSIZE;       // batch (clusters contiguous in x)
    const int r = blk % CSIZE;       // cluster rank

    const float* xb = xyz + (size_t)b * 3 * N;

    // Register-resident packed point slice + running scalar min-dist
    u64 PX[2], PY[2], PZ[2];
    float pd[PPT];
    const int base = r * (N / CSIZE) + t;
#pragma unroll
    for (int p = 0; p < 2; p++) {
        PX[p] = pk2f(xb[base + (2 * p) * T],         xb[base + (2 * p + 1) * T]);
        PY[p] = pk2f(xb[N + base + (2 * p) * T],     xb[N + base + (2 * p + 1) * T]);
        PZ[p] = pk2f(xb[2 * N + base + (2 * p) * T], xb[2 * N + base + (2 * p + 1) * T]);
    }
#pragma unroll
    for (int j = 0; j < PPT; j++) pd[j] = __int_as_float(0x7f800000);  // +inf

    const unsigned bar0 = smem_u32(&s_bar[0]);
    const unsigned bar1 = smem_u32(&s_bar[1]);
    if (t == 0) { mbar_init(bar0, 1); mbar_init(bar1, 1); }
    __syncthreads();
    // Arm both buffers' first phases BEFORE any remote can complete_tx
    // (remotes st.async only after cluster_sync, which needs our arrive,
    //  which follows these expects in thread 0's program order).
    if (t == 0) { mbar_expect(bar0, TXB); mbar_expect(bar1, TXB); }

    // Hoist DSMEM addresses for the exchange (warp 0, lanes 0..15 only)
    unsigned ra0 = 0, ra1 = 0, rb0 = 0, rb1 = 0;
    if (w == 0 && lane < CSIZE) {
        ra0 = mapa_u32(smem_u32(&s_cl[0][r]), (unsigned)lane);
        ra1 = mapa_u32(smem_u32(&s_cl[1][r]), (unsigned)lane);
        rb0 = mapa_u32(bar0, (unsigned)lane);
        rb1 = mapa_u32(bar1, (unsigned)lane);
    }
    cluster_sync_all();

    int cur = 0;
    float cx = xb[0], cy = xb[N], cz = xb[2 * N];

    for (int s = 0; s < K; s++) {
        if (r == 0 && t == 0) g_fps_idx[b * K + s] = cur;

        // ---- packed distance update + thread-local argmax (exact .rn mul/add) ----
        const u64 nx = pk2f(-cx, -cx);
        const u64 ny = pk2f(-cy, -cy);
        const u64 nz = pk2f(-cz, -cz);
        unsigned bestd = 0; int bestj = 0;
#pragma unroll
        for (int p = 0; p < 2; p++) {
            u64 dx = addx2(PX[p], nx);
            u64 dy = addx2(PY[p], ny);
            u64 dz = addx2(PZ[p], nz);
            u64 d2 = addx2(addx2(mulx2(dx, dx), mulx2(dy, dy)), mulx2(dz, dz));
            float da, db; upk2f(da, db, d2);
            float n0 = fminf(pd[2 * p], da);     pd[2 * p] = n0;
            unsigned u0 = __float_as_uint(n0);
            if (u0 > bestd) { bestd = u0; bestj = 2 * p; }       // strict > -> min idx
            float n1 = fminf(pd[2 * p + 1], db); pd[2 * p + 1] = n1;
            unsigned u1 = __float_as_uint(n1);
            if (u1 > bestd) { bestd = u1; bestj = 2 * p + 1; }
        }

        // ---- warp reduce: max dist; tie-break min idx; winner lane writes smem ----
        {
            const int pp = bestj >> 1;
            u64 sx = pp ? PX[1] : PX[0];
            u64 sy = pp ? PY[1] : PY[0];
            u64 sz = pp ? PZ[1] : PZ[0];
            float xl, xh, yl, yh, zl, zh;
            upk2f(xl, xh, sx); upk2f(yl, yh, sy); upk2f(zl, zh, sz);
            const bool hi = bestj & 1;
            const float bx = hi ? xh : xl;
            const float by = hi ? yh : yl;
            const float bz = hi ? zh : zl;
            const unsigned besti = (unsigned)(base + (bestj << 9));   // bestj * T

            unsigned wm = __reduce_max_sync(FULL, bestd);
            // cand packs (idx, lane): idx <= 32767 (15 bits), so <<5 fits 20 bits.
            // min over cand = min idx first (idx dominates lane), and low 5 bits
            // give the source lane -> no ballot/ffs/shfl needed at this stage.
            unsigned cand = (bestd == wm) ? ((besti << 5) | (unsigned)lane) : FULL;
            unsigned cm = __reduce_min_sync(FULL, cand);
            if (lane == (int)(cm & 31)) {
                s_warp[w].d = wm; s_warp[w].i = (int)(cm >> 5);
                s_warp[w].x = bx; s_warp[w].y = by; s_warp[w].z = bz;
            }
        }
        __syncthreads();

        const int par = s & 1;
        const unsigned ph = (unsigned)((s >> 1) & 1);
        const unsigned barp = par ? bar1 : bar0;

        // ---- block reduce (warp 0) + st.async CTA winner to all 16 cluster CTAs ----
        if (w == 0) {
            unsigned d = 0; int i = 0; float x = 0.f, y = 0.f, z = 0.f;
            if (lane < NW) {
                d = s_warp[lane].d; i = s_warp[lane].i;
                x = s_warp[lane].x; y = s_warp[lane].y; z = s_warp[lane].z;
            }
            unsigned m2 = __reduce_max_sync(FULL, d);
            unsigned c2 = (lane < NW && d == m2)
                              ? (((unsigned)i << 4) | (unsigned)lane) : FULL;
            unsigned cm2 = __reduce_min_sync(FULL, c2);
            const int s2 = (int)(cm2 & 15);
            const unsigned gi = cm2 >> 4;
            x = __shfl_sync(FULL, x, s2);
            y = __shfl_sync(FULL, y, s2);
            z = __shfl_sync(FULL, z, s2);
            if (lane < CSIZE) {
                const unsigned ra = par ? ra1 : ra0;
                const unsigned rb = par ? rb1 : rb0;
                st_async64(ra + 0,  pk2u(m2, gi),   rb);
                st_async64(ra + 8,  pk2f(x, y),     rb);
                st_async64(ra + 16, pk2f(z, 0.f),   rb);
            }
        }

        // ---- wait for all 16 CTAs' candidates; re-arm this buffer for s+2 ----
        mbar_wait(barp, ph);
        if (t == 0) mbar_expect(barp, TXB);

        // ---- warp-cooperative global winner (lanes 0..15 own one slot each) ----
        {
            unsigned d16 = 0; int i16 = 0; float fx = 0.f, fy = 0.f, fz = 0.f;
            if (lane < CSIZE) {
                const Slot& sl = s_cl[par][lane];
                d16 = sl.d; i16 = sl.i; fx = sl.x; fy = sl.y; fz = sl.z;
            }
            unsigned gm = __reduce_max_sync(FULL, d16);
            unsigned c8 = (lane < CSIZE && d16 == gm)
                              ? (((unsigned)i16 << 4) | (unsigned)lane) : FULL;
            unsigned cm8 = __reduce_min_sync(FULL, c8);
            const int sr = (int)(cm8 & 15);
            cur = (int)(cm8 >> 4);
            cx = __shfl_sync(FULL, fx, sr);
            cy = __shfl_sync(FULL, fy, sr);
            cz = __shfl_sync(FULL, fz, sr);
        }
    }
    cluster_sync_all();   // no CTA exits while peers may still touch its smem
}

// out = [node_static (B,3,K)] ++ [node_feature (B,C,K)], row-major, fp32
__global__ void __launch_bounds__(K)
gather_kernel(const float* __restrict__ xyz, const float* __restrict__ feat,
              float* __restrict__ out) {
    const int b = blockIdx.y;
    const int e = blockIdx.x;   // 0..2 -> xyz, 3..130 -> feature channel e-3
    const int k = threadIdx.x;
    const int id = g_fps_idx[b * K + k];
    if (e < 3) {
        out[((size_t)(b * 3 + e)) * K + k] =
            xyz[(size_t)b * 3 * N + (size_t)e * N + id];
    } else {
        const int c = e - 3;
        out[(size_t)B * 3 * K + ((size_t)(b * C + c)) * K + k] =
            feat[(size_t)b * C * N + (size_t)c * N + id];
    }
}

extern "C" void kernel_launch(void* const* d_in, const int* in_sizes, int n_in,
                              void* d_out, int out_size) {
    const float* xyz  = (const float*)d_in[0];   // [B,3,N] fp32
    const float* feat = (const float*)d_in[1];   // [B,C,N] fp32
    float* out = (float*)d_out;

    // 16-CTA clusters need the non-portable opt-in (idempotent; capture-safe).
    cudaFuncSetAttribute(fps_kernel,
                         cudaFuncAttributeNonPortableClusterSizeAllowed, 1);

    cudaLaunchConfig_t cfg = {};
    cfg.gridDim = dim3(B * CSIZE, 1, 1);
    cfg.blockDim = dim3(T, 1, 1);
    cfg.dynamicSmemBytes = 0;
    cfg.stream = 0;
    cudaLaunchAttribute attrs[1];
    attrs[0].id = cudaLaunchAttributeClusterDimension;
    attrs[0].val.clusterDim.x = CSIZE;
    attrs[0].val.clusterDim.y = 1;
    attrs[0].val.clusterDim.z = 1;
    cfg.attrs = attrs;
    cfg.numAttrs = 1;
    cudaLaunchKernelEx(&cfg, fps_kernel, xyz);

    gather_kernel<<<dim3(3 + C, B), K>>>(xyz, feat, out);
}

// round 4
// speedup vs baseline: 1.1733x; 1.1733x over previous
#include <cuda_runtime.h>
#include <cstdint>

#define B 8
#define N 32768
#define K 1024
#define C 128
#define CSIZE 16                 // CTAs per cluster (one cluster per batch)
#define T 128                    // threads per CTA
#define NW 4                     // warps per CTA
#define PPT 16                   // points per thread
#define NPAIR 8                  // f32x2 pairs per thread
#define SLOTS (CSIZE * NW)       // 64 warp-winner slots per CTA
#define TXB (SLOTS * 24)         // 64 senders x 3 st.async.b64 = 1536 B
#define FULL 0xffffffffu

typedef unsigned long long u64;

// FPS-selected indices, [B][K]
__device__ int g_fps_idx[B * K];

struct alignas(8) Slot {
    unsigned d;    // +0  fp32 bits of min-dist (nonneg -> uint order-isomorphic)
    int i;         // +4  point index (0..N-1)
    float x, y;    // +8, +12
    float z;       // +16
    unsigned pad;  // +20  (24B stride: 2-way LDS conflict on scan, acceptable)
};
static_assert(sizeof(Slot) == 24, "slot must be 24B");

// ---------------- PTX helpers ----------------
__device__ __forceinline__ unsigned smem_u32(const void* p) {
    return (unsigned)__cvta_generic_to_shared(p);
}
__device__ __forceinline__ unsigned mapa_u32(unsigned addr, unsigned rank) {
    unsigned r;
    asm("mapa.shared::cluster.u32 %0, %1, %2;" : "=r"(r) : "r"(addr), "r"(rank));
    return r;
}
__device__ __forceinline__ u64 pk2f(float lo, float hi) {
    u64 v; asm("mov.b64 %0, {%1, %2};" : "=l"(v) : "f"(lo), "f"(hi)); return v;
}
__device__ __forceinline__ u64 pk2u(unsigned lo, unsigned hi) {
    u64 v; asm("mov.b64 %0, {%1, %2};" : "=l"(v) : "r"(lo), "r"(hi)); return v;
}
__device__ __forceinline__ void upk2f(float& lo, float& hi, u64 v) {
    asm("mov.b64 {%0, %1}, %2;" : "=f"(lo), "=f"(hi) : "l"(v));
}
__device__ __forceinline__ u64 addx2(u64 a, u64 b) {
    u64 r; asm("add.rn.f32x2 %0, %1, %2;" : "=l"(r) : "l"(a), "l"(b)); return r;
}
__device__ __forceinline__ u64 mulx2(u64 a, u64 b) {
    u64 r; asm("mul.rn.f32x2 %0, %1, %2;" : "=l"(r) : "l"(a), "l"(b)); return r;
}
__device__ __forceinline__ void mbar_init(unsigned bar, unsigned cnt) {
    asm volatile("mbarrier.init.shared.b64 [%0], %1;" :: "r"(bar), "r"(cnt) : "memory");
}
__device__ __forceinline__ void mbar_expect(unsigned bar, unsigned tx) {
    asm volatile("mbarrier.arrive.expect_tx.shared.b64 _, [%0], %1;"
                 :: "r"(bar), "r"(tx) : "memory");
}
__device__ __forceinline__ void st_async64(unsigned raddr, u64 v, unsigned rbar) {
    asm volatile(
        "st.async.shared::cluster.mbarrier::complete_tx::bytes.b64 [%0], %1, [%2];"
        :: "r"(raddr), "l"(v), "r"(rbar) : "memory");
}
__device__ __forceinline__ void mbar_wait(unsigned bar, unsigned ph) {
    asm volatile(
        "{\n\t"
        ".reg .pred P;\n\t"
        "WL_%=:\n\t"
        "mbarrier.try_wait.parity.acquire.cluster.shared::cta.b64 P, [%0], %1, 0x989680;\n\t"
        "@P bra WD_%=;\n\t"
        "bra WL_%=;\n\t"
        "WD_%=:\n\t"
        "}"
        :: "r"(bar), "r"(ph) : "memory");
}
__device__ __forceinline__ void cluster_sync_all() {
    asm volatile("barrier.cluster.arrive.aligned;" ::: "memory");
    asm volatile("barrier.cluster.wait.aligned;" ::: "memory");
}
// 8-way u64 select by 3-bit p
__device__ __forceinline__ u64 sel8(const u64* A, int p) {
    u64 a0 = (p & 1) ? A[1] : A[0];
    u64 a1 = (p & 1) ? A[3] : A[2];
    u64 a2 = (p & 1) ? A[5] : A[4];
    u64 a3 = (p & 1) ? A[7] : A[6];
    u64 b0 = (p & 2) ? a1 : a0;
    u64 b1 = (p & 2) ? a3 : a2;
    return (p & 4) ? b1 : b0;
}

__global__ void __launch_bounds__(T, 1)
fps_kernel(const float* __restrict__ xyz) {
    // 64 warp-winner slots (16 CTAs x 4 warps), double-buffered, + 2 mbarriers
    __shared__ Slot s_all[2][SLOTS];
    __shared__ u64 s_bar[2];

    const int t = threadIdx.x;
    const int lane = t & 31;
    const int w = t >> 5;
    const int blk = blockIdx.x;
    const int b = blk / CSIZE;       // batch (clusters contiguous in x)
    const int r = blk % CSIZE;       // cluster rank

    const float* xb = xyz + (size_t)b * 3 * N;

    // Register-resident packed point slice + running scalar min-dist
    u64 PX[NPAIR], PY[NPAIR], PZ[NPAIR];
    float pd[PPT];
    const int base = r * (N / CSIZE) + t;
#pragma unroll
    for (int p = 0; p < NPAIR; p++) {
        PX[p] = pk2f(xb[base + (2 * p) * T],         xb[base + (2 * p + 1) * T]);
        PY[p] = pk2f(xb[N + base + (2 * p) * T],     xb[N + base + (2 * p + 1) * T]);
        PZ[p] = pk2f(xb[2 * N + base + (2 * p) * T], xb[2 * N + base + (2 * p + 1) * T]);
    }
#pragma unroll
    for (int j = 0; j < PPT; j++) pd[j] = __int_as_float(0x7f800000);  // +inf

    const unsigned bar0 = smem_u32(&s_bar[0]);
    const unsigned bar1 = smem_u32(&s_bar[1]);
    if (t == 0) { mbar_init(bar0, 1); mbar_init(bar1, 1); }
    __syncthreads();
    // Arm both buffers' first phases BEFORE any remote can complete_tx
    // (remotes st.async only after cluster_sync below).
    if (t == 0) { mbar_expect(bar0, TXB); mbar_expect(bar1, TXB); }

    // Hoist DSMEM destination addresses: lane q of warp w delivers this CTA's
    // warp-w winner into CTA q's slot [r*NW + w].
    unsigned ra0 = 0, ra1 = 0, rb0 = 0, rb1 = 0;
    if (lane < CSIZE) {
        const int slot = r * NW + w;
        ra0 = mapa_u32(smem_u32(&s_all[0][slot]), (unsigned)lane);
        ra1 = mapa_u32(smem_u32(&s_all[1][slot]), (unsigned)lane);
        rb0 = mapa_u32(bar0, (unsigned)lane);
        rb1 = mapa_u32(bar1, (unsigned)lane);
    }
    cluster_sync_all();

    int cur = 0;
    float cx = xb[0], cy = xb[N], cz = xb[2 * N];

    for (int s = 0; s < K; s++) {
        if (r == 0 && t == 0) g_fps_idx[b * K + s] = cur;

        // ---- packed distance update + thread-local argmax (exact .rn mul/add) ----
        const u64 nx = pk2f(-cx, -cx);
        const u64 ny = pk2f(-cy, -cy);
        const u64 nz = pk2f(-cz, -cz);
        unsigned bestd = 0; int bestj = 0;
#pragma unroll
        for (int p = 0; p < NPAIR; p++) {
            u64 dx = addx2(PX[p], nx);
            u64 dy = addx2(PY[p], ny);
            u64 dz = addx2(PZ[p], nz);
            u64 d2 = addx2(addx2(mulx2(dx, dx), mulx2(dy, dy)), mulx2(dz, dz));
            float da, db; upk2f(da, db, d2);
            float n0 = fminf(pd[2 * p], da);     pd[2 * p] = n0;
            unsigned u0 = __float_as_uint(n0);
            if (u0 > bestd) { bestd = u0; bestj = 2 * p; }       // strict > -> min idx
            float n1 = fminf(pd[2 * p + 1], db); pd[2 * p + 1] = n1;
            unsigned u1 = __float_as_uint(n1);
            if (u1 > bestd) { bestd = u1; bestj = 2 * p + 1; }
        }

        // ---- resolve winner coords (3-bit select tree) ----
        float bx, by, bz;
        {
            const int pp = bestj >> 1;
            float xl, xh, yl, yh, zl, zh;
            upk2f(xl, xh, sel8(PX, pp));
            upk2f(yl, yh, sel8(PY, pp));
            upk2f(zl, zh, sel8(PZ, pp));
            const bool hi = bestj & 1;
            bx = hi ? xh : xl; by = hi ? yh : yl; bz = hi ? zh : zl;
        }
        const unsigned besti = (unsigned)(base + (bestj << 7));   // bestj * T

        // ---- warp reduce: max dist, tie-break min idx (idx<<5|lane packing) ----
        unsigned wm = __reduce_max_sync(FULL, bestd);
        unsigned cand = (bestd == wm) ? ((besti << 5) | (unsigned)lane) : FULL;
        unsigned cm = __reduce_min_sync(FULL, cand);
        const int sr = (int)(cm & 31);
        const unsigned wi = cm >> 5;
        bx = __shfl_sync(FULL, bx, sr);
        by = __shfl_sync(FULL, by, sr);
        bz = __shfl_sync(FULL, bz, sr);

        const int par = s & 1;
        const unsigned ph = (unsigned)((s >> 1) & 1);
        const unsigned barp = par ? bar1 : bar0;

        // ---- all-to-all: lanes 0..15 deliver warp winner to every cluster CTA ----
        if (lane < CSIZE) {
            const unsigned ra = par ? ra1 : ra0;
            const unsigned rb = par ? rb1 : rb0;
            st_async64(ra + 0,  pk2u(wm, wi),  rb);
            st_async64(ra + 8,  pk2f(bx, by),  rb);
            st_async64(ra + 16, pk2f(bz, 0.f), rb);
        }

        // ---- wait for all 64 warp winners; re-arm this buffer for s+2 ----
        mbar_wait(barp, ph);
        if (t == 0) mbar_expect(barp, TXB);

        // ---- warp-cooperative global winner over 64 slots (2 per lane) ----
        {
            const Slot* sp = s_all[par];
            const unsigned d0 = sp[lane].d;        const int i0 = sp[lane].i;
            const unsigned d1 = sp[lane + 32].d;   const int i1 = sp[lane + 32].i;
            const bool take1 = (d1 > d0) || (d1 == d0 && i1 < i0);
            const unsigned dl = take1 ? d1 : d0;
            const unsigned il = take1 ? (unsigned)i1 : (unsigned)i0;
            const unsigned sl = take1 ? (unsigned)(lane + 32) : (unsigned)lane;

            unsigned gm = __reduce_max_sync(FULL, dl);
            unsigned c2 = (dl == gm) ? ((il << 6) | sl) : FULL;   // idx(15b)<<6|slot(6b)
            unsigned cm2 = __reduce_min_sync(FULL, c2);
            const int slotw = (int)(cm2 & 63);
            cur = (int)(cm2 >> 6);
            // broadcast LDS of winning slot's coords (same address, no conflict)
            cx = sp[slotw].x; cy = sp[slotw].y; cz = sp[slotw].z;
        }
    }
    cluster_sync_all();   // no CTA exits while peers may still touch its smem
}

// out = [node_static (B,3,K)] ++ [node_feature (B,C,K)], row-major, fp32
__global__ void __launch_bounds__(K)
gather_kernel(const float* __restrict__ xyz, const float* __restrict__ feat,
              float* __restrict__ out) {
    const int b = blockIdx.y;
    const int e = blockIdx.x;   // 0..2 -> xyz, 3..130 -> feature channel e-3
    const int k = threadIdx.x;
    const int id = g_fps_idx[b * K + k];
    if (e < 3) {
        out[((size_t)(b * 3 + e)) * K + k] =
            xyz[(size_t)b * 3 * N + (size_t)e * N + id];
    } else {
        const int c = e - 3;
        out[(size_t)B * 3 * K + ((size_t)(b * C + c)) * K + k] =
            feat[(size_t)b * C * N + (size_t)c * N + id];
    }
}

extern "C" void kernel_launch(void* const* d_in, const int* in_sizes, int n_in,
                              void* d_out, int out_size) {
    const float* xyz  = (const float*)d_in[0];   // [B,3,N] fp32
    const float* feat = (const float*)d_in[1];   // [B,C,N] fp32
    float* out = (float*)d_out;

    // 16-CTA clusters need the non-portable opt-in (idempotent; capture-safe).
    cudaFuncSetAttribute(fps_kernel,
                         cudaFuncAttributeNonPortableClusterSizeAllowed, 1);

    cudaLaunchConfig_t cfg = {};
    cfg.gridDim = dim3(B * CSIZE, 1, 1);
    cfg.blockDim = dim3(T, 1, 1);
    cfg.dynamicSmemBytes = 0;
    cfg.stream = 0;
    cudaLaunchAttribute attrs[1];
    attrs[0].id = cudaLaunchAttributeClusterDimension;
    attrs[0].val.clusterDim.x = CSIZE;
    attrs[0].val.clusterDim.y = 1;
    attrs[0].val.clusterDim.z = 1;
    cfg.attrs = attrs;
    cfg.numAttrs = 1;
    cudaLaunchKernelEx(&cfg, fps_kernel, xyz);

    gather_kernel<<<dim3(3 + C, B), K>>>(xyz, feat, out);
}